// round 10
// baseline (speedup 1.0000x reference)
#include <cuda_runtime.h>
#include <cuda_bf16.h>
#include <math.h>

// ---------------------------------------------------------------------------
// Problem constants
// ---------------------------------------------------------------------------
constexpr int kB  = 32, kC = 3, kH = 224, kW = 224;
constexpr int kHW = kH * kW;          // 50176
constexpr int kS  = 256, kD = 768, kL = 12, kNH = 12, kHD = 64;
constexpr int kMLP = 3072, kNC = 1000;
constexpr int kN  = kS + 1;           // 257 tokens
constexpr int kM  = kB * kN;          // 8224 rows
constexpr int kQKV = 3 * kD;          // 2304

// ---------------------------------------------------------------------------
// Scratch (static device globals -- allowed; runtime allocation is not)
// ---------------------------------------------------------------------------
__device__ float g_x[kM * kD];
__device__ float g_h[kM * kD];
__device__ float g_qkv[kM * kQKV];
__device__ float g_att[kM * kD];
__device__ float g_mlp[kM * kMLP];
__device__ float g_seg[kB * kS * kC];
__device__ float g_cls[kB * kD];

// ---------------------------------------------------------------------------
// Helpers
// ---------------------------------------------------------------------------
__device__ __forceinline__ float gelu_exact(float x) {
    return 0.5f * x * (1.0f + erff(x * 0.70710678118654752440f));
}

__device__ __forceinline__ unsigned packbf(float a, float b) {
    __nv_bfloat162 t = __floats2bfloat162_rn(a, b);
    return *reinterpret_cast<unsigned*>(&t);
}

// bf16 m16n8k16 MMA, fp32 accumulate
__device__ __forceinline__ void mma_bf16(float c[4], const unsigned a[4], const unsigned b[2]) {
    asm volatile(
        "mma.sync.aligned.m16n8k16.row.col.f32.bf16.bf16.f32 "
        "{%0,%1,%2,%3}, {%4,%5,%6,%7}, {%8,%9}, {%0,%1,%2,%3};\n"
        : "+f"(c[0]), "+f"(c[1]), "+f"(c[2]), "+f"(c[3])
        : "r"(a[0]), "r"(a[1]), "r"(a[2]), "r"(a[3]), "r"(b[0]), "r"(b[1]));
}

__device__ __forceinline__ void ldsm_x4(unsigned r[4], unsigned saddr) {
    asm volatile(
        "ldmatrix.sync.aligned.m8n8.x4.shared.b16 {%0,%1,%2,%3}, [%4];\n"
        : "=r"(r[0]), "=r"(r[1]), "=r"(r[2]), "=r"(r[3]) : "r"(saddr));
}

// ---------------------------------------------------------------------------
// 1) Superpixel segment sums: one block per batch image, smem histogram
// ---------------------------------------------------------------------------
__global__ void seg_sum_kernel(const float* __restrict__ img, const int* __restrict__ seg) {
    __shared__ float sm[kS * kC];
    const int b = blockIdx.x;
    for (int i = threadIdx.x; i < kS * kC; i += blockDim.x) sm[i] = 0.f;
    __syncthreads();
    const int*   sb = seg + (size_t)b * kHW;
    const float* i0 = img + (size_t)(b * kC + 0) * kHW;
    const float* i1 = img + (size_t)(b * kC + 1) * kHW;
    const float* i2 = img + (size_t)(b * kC + 2) * kHW;
    for (int p = threadIdx.x; p < kHW; p += blockDim.x) {
        int s = sb[p];
        atomicAdd(&sm[s * 3 + 0], i0[p]);
        atomicAdd(&sm[s * 3 + 1], i1[p]);
        atomicAdd(&sm[s * 3 + 2], i2[p]);
    }
    __syncthreads();
    for (int i = threadIdx.x; i < kS * kC; i += blockDim.x) g_seg[b * kS * kC + i] = sm[i];
}

// ---------------------------------------------------------------------------
// 2) Build x = concat(cls, seg_mean @ w_fe + b_fe) + pos_embed
// ---------------------------------------------------------------------------
__global__ void embed_kernel(const float* __restrict__ w_fe, const float* __restrict__ b_fe,
                             const float* __restrict__ cls_t, const float* __restrict__ pos) {
    const int tok = blockIdx.x;
    const int b = tok / kN, n = tok % kN;
    float s0 = 0.f, s1 = 0.f, s2 = 0.f;
    if (n > 0) {
        const float* sp = g_seg + (size_t)(b * kS + (n - 1)) * 3;
        const float inv = 1.0f / (float)kHW;
        s0 = sp[0] * inv; s1 = sp[1] * inv; s2 = sp[2] * inv;
    }
    float* xr = g_x + (size_t)tok * kD;
    for (int d = threadIdx.x; d < kD; d += blockDim.x) {
        float pv = pos[n * kD + d];
        float v;
        if (n == 0) v = cls_t[d] + pv;
        else        v = b_fe[d] + pv + s0 * w_fe[d] + s1 * w_fe[kD + d] + s2 * w_fe[2 * kD + d];
        xr[d] = v;
    }
}

// ---------------------------------------------------------------------------
// 3) LayerNorm (one block per row, D=768, 256 threads x 3 elems)
// ---------------------------------------------------------------------------
__global__ __launch_bounds__(256) void ln_kernel(const float* __restrict__ x, float* __restrict__ y,
                          const float* __restrict__ gw, const float* __restrict__ bw,
                          long xstride, long ystride) {
    const int row = blockIdx.x;
    const float* xr = x + (long)row * xstride;
    float*       yr = y + (long)row * ystride;
    const int tid = threadIdx.x;
    float v0 = xr[tid], v1 = xr[tid + 256], v2 = xr[tid + 512];
    __shared__ float red[8];

    float s = v0 + v1 + v2;
    #pragma unroll
    for (int o = 16; o > 0; o >>= 1) s += __shfl_down_sync(0xffffffffu, s, o);
    if ((tid & 31) == 0) red[tid >> 5] = s;
    __syncthreads();
    if (tid < 8) {
        float t = red[tid];
        #pragma unroll
        for (int o = 4; o > 0; o >>= 1) t += __shfl_down_sync(0xffu, t, o);
        if (tid == 0) red[0] = t;
    }
    __syncthreads();
    const float m = red[0] * (1.0f / kD);
    __syncthreads();

    const float d0 = v0 - m, d1 = v1 - m, d2 = v2 - m;
    float q = d0 * d0 + d1 * d1 + d2 * d2;
    #pragma unroll
    for (int o = 16; o > 0; o >>= 1) q += __shfl_down_sync(0xffffffffu, q, o);
    if ((tid & 31) == 0) red[tid >> 5] = q;
    __syncthreads();
    if (tid < 8) {
        float t = red[tid];
        #pragma unroll
        for (int o = 4; o > 0; o >>= 1) t += __shfl_down_sync(0xffu, t, o);
        if (tid == 0) red[0] = t;
    }
    __syncthreads();
    const float inv = rsqrtf(red[0] * (1.0f / kD) + 1e-6f);

    yr[tid]       = d0 * inv * gw[tid]       + bw[tid];
    yr[tid + 256] = d1 * inv * gw[tid + 256] + bw[tid + 256];
    yr[tid + 512] = d2 * inv * gw[tid + 512] + bw[tid + 512];
}

// ---------------------------------------------------------------------------
// 4) Split-bf16 GEMM with ldmatrix fragment loads.
//    BM=BN=128, BK=32, 256 threads, warp tile 32x64, m16n8k16.bf16 hi/lo split.
//    A smem: [128 rows][20] u32 (16 K-pairs + pad)  -> 2560 u32  (80B rows, 16B aligned)
//    B smem: [128 n]  [20] u32 (16 K-pairs + pad)   -> 2560 u32  (n-major, 80B rows)
//    Per buffer: Ah 2560 | Al 2560 | Bh 2560 | Bl 2560 = 10240 u32 (40960 B).
//    Two buffers = 81920 B; 2 CTAs/SM = 163840 B < 228KB.
// ---------------------------------------------------------------------------
constexpr int BUF_U32   = 10240;
constexpr int GEMM_SMEM = 2 * BUF_U32 * 4;   // 81920 B

template <int OP>   // 0: +bias   1: +bias, gelu   2: +bias, +res
__global__ __launch_bounds__(256, 2) void gemm_kernel(
    const float* __restrict__ A, const float* __restrict__ Wm,
    const float* __restrict__ bias, const float* __restrict__ res,
    float* __restrict__ Cout, int M, int N, int K)
{
    extern __shared__ unsigned smemu[];
    const unsigned sbase = (unsigned)__cvta_generic_to_shared(smemu);

    const int tid = threadIdx.x;
    const int wid = tid >> 5, lane = tid & 31;
    const int gp = lane >> 2, tg = lane & 3;
    const int wm = (wid >> 1) * 32;     // 4 warps along M
    const int wn = (wid & 1) * 64;      // 2 warps along N
    const int m0 = blockIdx.y * 128;
    const int n0 = blockIdx.x * 128;

    float c[2][8][4];
    #pragma unroll
    for (int i = 0; i < 2; i++)
        #pragma unroll
        for (int j = 0; j < 8; j++)
            #pragma unroll
            for (int r = 0; r < 4; r++) c[i][j][r] = 0.f;

    // ldmatrix per-lane source rows (u32 offsets within a buffer); both strides 20.
    const int lr = lane & 7, sub = lane >> 3;
    const unsigned aoff = (unsigned)((wm + lr + (sub & 1) * 8) * 20 + (sub >> 1) * 4);
    const unsigned boff = (unsigned)((wn + lr + (sub >> 1) * 8) * 20 + (sub & 1) * 4);

    // loader indices
    const int arow = tid >> 3, ac4 = tid & 7;      // A: 4 rows-of-32, float4 col
    const int bq   = tid >> 5;                     // B: q-group = warp id (0..7)

    float4 apf[4];
    float  bpf0[2][4], bpf1[2][4];

    const int nK = K >> 5;

    auto prefetch = [&](int k0) {
        #pragma unroll
        for (int p = 0; p < 4; p++) {
            const int grow = m0 + p * 32 + arow;
            if (grow < M) apf[p] = *(const float4*)(A + (size_t)grow * K + k0 + ac4 * 4);
            else          apf[p] = make_float4(0.f, 0.f, 0.f, 0.f);
        }
        #pragma unroll
        for (int p = 0; p < 2; p++) {
            const int q = p * 8 + bq;
            const float* r0 = Wm + (size_t)(k0 + 2 * q) * N + n0 + lane;
            const float* r1 = r0 + N;
            #pragma unroll
            for (int j = 0; j < 4; j++) {
                bpf0[p][j] = r0[32 * j];
                bpf1[p][j] = r1[32 * j];
            }
        }
    };

    auto store_buf = [&](int buf) {
        unsigned* Ah = smemu + buf * BUF_U32;
        unsigned* Al = Ah + 2560;
        unsigned* Bh = Ah + 5120;
        unsigned* Bl = Ah + 7680;
        #pragma unroll
        for (int p = 0; p < 4; p++) {
            const int r = p * 32 + arow;
            float v[4] = {apf[p].x, apf[p].y, apf[p].z, apf[p].w};
            float hf[4], lf[4];
            #pragma unroll
            for (int i = 0; i < 4; i++) {
                hf[i] = __bfloat162float(__float2bfloat16(v[i]));
                lf[i] = v[i] - hf[i];
            }
            Ah[r * 20 + ac4 * 2]     = packbf(hf[0], hf[1]);
            Ah[r * 20 + ac4 * 2 + 1] = packbf(hf[2], hf[3]);
            Al[r * 20 + ac4 * 2]     = packbf(lf[0], lf[1]);
            Al[r * 20 + ac4 * 2 + 1] = packbf(lf[2], lf[3]);
        }
        #pragma unroll
        for (int p = 0; p < 2; p++) {
            const int q = p * 8 + bq;
            #pragma unroll
            for (int j = 0; j < 4; j++) {
                const int n = lane + 32 * j;
                float h0 = __bfloat162float(__float2bfloat16(bpf0[p][j]));
                float h1 = __bfloat162float(__float2bfloat16(bpf1[p][j]));
                Bh[n * 20 + q] = packbf(h0, h1);
                Bl[n * 20 + q] = packbf(bpf0[p][j] - h0, bpf1[p][j] - h1);
            }
        }
    };

    prefetch(0);
    store_buf(0);
    __syncthreads();

    for (int kt = 0; kt < nK; kt++) {
        if (kt + 1 < nK) prefetch((kt + 1) << 5);

        const unsigned bufb = sbase + (unsigned)((kt & 1) * BUF_U32) * 4u;

        #pragma unroll
        for (int kk = 0; kk < 2; kk++) {
            unsigned ah[2][4], al[2][4], bb[8][2];
            #pragma unroll
            for (int mi = 0; mi < 2; mi++) {
                const unsigned ao = (aoff + (unsigned)(kk * 8 + mi * 320)) * 4u;
                ldsm_x4(ah[mi], bufb + ao);             // Ah at offset 0
                ldsm_x4(al[mi], bufb + 2560u * 4u + ao);
            }
            // B hi: 4 ldmatrix.x4, each covers n-blocks (2np, 2np+1)
            #pragma unroll
            for (int np = 0; np < 4; np++) {
                unsigned r[4];
                const unsigned bo = (boff + (unsigned)(kk * 8 + np * 320)) * 4u;
                ldsm_x4(r, bufb + 5120u * 4u + bo);
                bb[2 * np][0] = r[0]; bb[2 * np][1] = r[1];
                bb[2 * np + 1][0] = r[2]; bb[2 * np + 1][1] = r[3];
            }
            #pragma unroll
            for (int mi = 0; mi < 2; mi++)
                #pragma unroll
                for (int ni = 0; ni < 8; ni++) {
                    mma_bf16(c[mi][ni], ah[mi], bb[ni]);   // hi*hi
                    mma_bf16(c[mi][ni], al[mi], bb[ni]);   // lo*hi
                }
            // B lo
            #pragma unroll
            for (int np = 0; np < 4; np++) {
                unsigned r[4];
                const unsigned bo = (boff + (unsigned)(kk * 8 + np * 320)) * 4u;
                ldsm_x4(r, bufb + 7680u * 4u + bo);
                bb[2 * np][0] = r[0]; bb[2 * np][1] = r[1];
                bb[2 * np + 1][0] = r[2]; bb[2 * np + 1][1] = r[3];
            }
            #pragma unroll
            for (int mi = 0; mi < 2; mi++)
                #pragma unroll
                for (int ni = 0; ni < 8; ni++)
                    mma_bf16(c[mi][ni], ah[mi], bb[ni]);   // hi*lo
        }

        if (kt + 1 < nK) store_buf((kt + 1) & 1);
        __syncthreads();
    }

    #pragma unroll
    for (int mi = 0; mi < 2; mi++)
        #pragma unroll
        for (int ni = 0; ni < 8; ni++) {
            const int col = n0 + wn + ni * 8 + tg * 2;
            const float b0 = bias[col], b1 = bias[col + 1];
            #pragma unroll
            for (int hh = 0; hh < 2; hh++) {
                const int row = m0 + wm + mi * 16 + gp + hh * 8;
                if (row < M) {
                    float v0 = c[mi][ni][hh * 2 + 0] + b0;
                    float v1 = c[mi][ni][hh * 2 + 1] + b1;
                    if (OP == 1) { v0 = gelu_exact(v0); v1 = gelu_exact(v1); }
                    if (OP == 2) {
                        float2 rr = *(const float2*)(res + (size_t)row * N + col);
                        v0 += rr.x; v1 += rr.y;
                    }
                    *(float2*)(Cout + (size_t)row * N + col) = make_float2(v0, v1);
                }
            }
        }
}

// ---------------------------------------------------------------------------
// 5) Fused attention, 4-row register blocking per warp; K rows read as float4.
//    smem floats: Ks[257][68] -> 17476 | Vs +17476 | Q4 @34952 (8x256) |
//                 P4 @37000 (8x1152) -> total 46216 floats.
// ---------------------------------------------------------------------------
constexpr int ATTN_SMEM = 46216 * 4;   // 184864 B

__global__ __launch_bounds__(256) void attn_kernel() {
    extern __shared__ float sm[];
    float* Ks = sm;                      // [257][68]
    float* Vs = sm + 17476;              // [257][68]
    float* Q4 = sm + 34952;              // [8 warps][64 k][4 rows]
    float* P4 = sm + 37000;              // [8 warps][288 j][4 rows]

    const int b = blockIdx.x / kNH, hh = blockIdx.x % kNH;
    const int tid = threadIdx.x, w = tid >> 5, lane = tid & 31;
    const float* base = g_qkv + (size_t)b * kN * kQKV + hh * kHD;

    for (int i = tid; i < kN * kHD; i += 256) {
        const int n = i >> 6, d = i & 63;
        Ks[n * 68 + d] = base[(size_t)n * kQKV + kD + d];
        Vs[n * 68 + d] = base[(size_t)n * kQKV + 2 * kD + d];
    }
    __syncthreads();

    float* Q4w = Q4 + w * 256;
    float* P4w = P4 + w * 1152;

    for (int pass = 0; pass < 9; pass++) {
        const int r0 = pass * 32 + w * 4;

        // stage Q for 4 rows (clamped; extra rows never stored)
        #pragma unroll
        for (int hk = 0; hk < 2; hk++) {
            const int k = hk * 32 + lane;
            #pragma unroll
            for (int rr = 0; rr < 4; rr++) {
                int r = r0 + rr; if (r >= kN) r = kN - 1;
                Q4w[k * 4 + rr] = base[(size_t)r * kQKV + k];
            }
        }
        __syncwarp();

        // scores: lane owns j = t*32+lane, 4 rows at once
        float s[4][9];
        #pragma unroll
        for (int t = 0; t < 9; t++) {
            const int j = t * 32 + lane;
            const int jj = (j < kN) ? j : 0;
            const float4* kr4 = (const float4*)(Ks + jj * 68);
            float a0 = 0.f, a1 = 0.f, a2 = 0.f, a3 = 0.f;
            #pragma unroll 4
            for (int k4 = 0; k4 < 16; k4++) {
                const float4 kv = kr4[k4];
                const float kvs[4] = {kv.x, kv.y, kv.z, kv.w};
                #pragma unroll
                for (int u = 0; u < 4; u++) {
                    const float4 qv = *(const float4*)(Q4w + (k4 * 4 + u) * 4);
                    a0 += qv.x * kvs[u]; a1 += qv.y * kvs[u];
                    a2 += qv.z * kvs[u]; a3 += qv.w * kvs[u];
                }
            }
            const float ninf = -__int_as_float(0x7f800000);
            s[0][t] = (j < kN) ? a0 * 0.125f : ninf;
            s[1][t] = (j < kN) ? a1 * 0.125f : ninf;
            s[2][t] = (j < kN) ? a2 * 0.125f : ninf;
            s[3][t] = (j < kN) ? a3 * 0.125f : ninf;
        }

        // softmax per row; write probs as float4-per-j
        #pragma unroll
        for (int rr = 0; rr < 4; rr++) {
            float mx = s[rr][0];
            #pragma unroll
            for (int t = 1; t < 9; t++) mx = fmaxf(mx, s[rr][t]);
            #pragma unroll
            for (int o = 16; o > 0; o >>= 1) mx = fmaxf(mx, __shfl_xor_sync(0xffffffffu, mx, o));
            float sum = 0.f;
            #pragma unroll
            for (int t = 0; t < 9; t++) { s[rr][t] = __expf(s[rr][t] - mx); sum += s[rr][t]; }
            #pragma unroll
            for (int o = 16; o > 0; o >>= 1) sum += __shfl_xor_sync(0xffffffffu, sum, o);
            const float inv = 1.0f / sum;
            #pragma unroll
            for (int t = 0; t < 9; t++) P4w[(t * 32 + lane) * 4 + rr] = s[rr][t] * inv;
        }
        __syncwarp();

        // AV: lane owns dims (lane, lane+32); 4 rows at once
        float o0[4] = {0.f, 0.f, 0.f, 0.f};
        float o1[4] = {0.f, 0.f, 0.f, 0.f};
        #pragma unroll 4
        for (int j = 0; j < kN; j++) {
            const float v0 = Vs[j * 68 + lane];
            const float v1 = Vs[j * 68 + 32 + lane];
            const float4 p = *(const float4*)(P4w + j * 4);
            o0[0] += p.x * v0; o1[0] += p.x * v1;
            o0[1] += p.y * v0; o1[1] += p.y * v1;
            o0[2] += p.z * v0; o1[2] += p.z * v1;
            o0[3] += p.w * v0; o1[3] += p.w * v1;
        }

        #pragma unroll
        for (int rr = 0; rr < 4; rr++) {
            const int r = r0 + rr;
            if (r < kN) {
                float* orow = g_att + (size_t)(b * kN + r) * kD + hh * kHD;
                orow[lane]      = o0[rr];
                orow[lane + 32] = o1[rr];
            }
        }
        __syncwarp();
    }
}

// ---------------------------------------------------------------------------
// 6) Head: out[b, c] = cls_ln[b] . head_w[:, c] + head_b[c]
// ---------------------------------------------------------------------------
__global__ void head_kernel(const float* __restrict__ hw, const float* __restrict__ hb,
                            float* __restrict__ out) {
    __shared__ float xs[kD];
    const int b = blockIdx.y;
    const int col = blockIdx.x * 256 + threadIdx.x;
    for (int i = threadIdx.x; i < kD; i += 256) xs[i] = g_cls[b * kD + i];
    __syncthreads();
    if (col < kNC) {
        float acc = hb[col];
        #pragma unroll 4
        for (int k = 0; k < kD; k++) acc += xs[k] * hw[(size_t)k * kNC + col];
        out[(size_t)b * kNC + col] = acc;
    }
}

// ---------------------------------------------------------------------------
// Launch
// ---------------------------------------------------------------------------
extern "C" void kernel_launch(void* const* d_in, const int* in_sizes, int n_in,
                              void* d_out, int out_size) {
    const float* img    = (const float*)d_in[0];
    const int*   seg    = (const int*)  d_in[1];
    const float* w_fe   = (const float*)d_in[2];
    const float* b_fe   = (const float*)d_in[3];
    const float* cls_t  = (const float*)d_in[4];
    const float* pos    = (const float*)d_in[5];
    const float* ln1_g  = (const float*)d_in[6];
    const float* ln1_b  = (const float*)d_in[7];
    const float* qkv_w  = (const float*)d_in[8];
    const float* qkv_b  = (const float*)d_in[9];
    const float* proj_w = (const float*)d_in[10];
    const float* proj_b = (const float*)d_in[11];
    const float* ln2_g  = (const float*)d_in[12];
    const float* ln2_b  = (const float*)d_in[13];
    const float* mlp_w1 = (const float*)d_in[14];
    const float* mlp_b1 = (const float*)d_in[15];
    const float* mlp_w2 = (const float*)d_in[16];
    const float* mlp_b2 = (const float*)d_in[17];
    const float* norm_g = (const float*)d_in[18];
    const float* norm_b = (const float*)d_in[19];
    const float* head_w = (const float*)d_in[20];
    const float* head_b = (const float*)d_in[21];

    cudaFuncSetAttribute(attn_kernel,    cudaFuncAttributeMaxDynamicSharedMemorySize, ATTN_SMEM);
    cudaFuncSetAttribute(gemm_kernel<0>, cudaFuncAttributeMaxDynamicSharedMemorySize, GEMM_SMEM);
    cudaFuncSetAttribute(gemm_kernel<1>, cudaFuncAttributeMaxDynamicSharedMemorySize, GEMM_SMEM);
    cudaFuncSetAttribute(gemm_kernel<2>, cudaFuncAttributeMaxDynamicSharedMemorySize, GEMM_SMEM);

    float *px, *ph, *pq, *pa, *pm, *pc;
    cudaGetSymbolAddress((void**)&px, g_x);
    cudaGetSymbolAddress((void**)&ph, g_h);
    cudaGetSymbolAddress((void**)&pq, g_qkv);
    cudaGetSymbolAddress((void**)&pa, g_att);
    cudaGetSymbolAddress((void**)&pm, g_mlp);
    cudaGetSymbolAddress((void**)&pc, g_cls);

    seg_sum_kernel<<<kB, 256>>>(img, seg);
    embed_kernel<<<kM, 256>>>(w_fe, b_fe, cls_t, pos);

    const dim3 gQKV(kQKV / 128, (kM + 127) / 128);
    const dim3 gD  (kD   / 128, (kM + 127) / 128);
    const dim3 gMLP(kMLP / 128, (kM + 127) / 128);

    for (int l = 0; l < kL; l++) {
        ln_kernel<<<kM, 256>>>(px, ph, ln1_g + (size_t)l * kD, ln1_b + (size_t)l * kD, kD, kD);
        gemm_kernel<0><<<gQKV, 256, GEMM_SMEM>>>(ph, qkv_w + (size_t)l * kD * kQKV,
                                                 qkv_b + (size_t)l * kQKV, nullptr, pq,
                                                 kM, kQKV, kD);
        attn_kernel<<<kB * kNH, 256, ATTN_SMEM>>>();
        gemm_kernel<2><<<gD, 256, GEMM_SMEM>>>(pa, proj_w + (size_t)l * kD * kD,
                                               proj_b + (size_t)l * kD, px, px,
                                               kM, kD, kD);
        ln_kernel<<<kM, 256>>>(px, ph, ln2_g + (size_t)l * kD, ln2_b + (size_t)l * kD, kD, kD);
        gemm_kernel<1><<<gMLP, 256, GEMM_SMEM>>>(ph, mlp_w1 + (size_t)l * kD * kMLP,
                                                 mlp_b1 + (size_t)l * kMLP, nullptr, pm,
                                                 kM, kMLP, kD);
        gemm_kernel<2><<<gD, 256, GEMM_SMEM>>>(pm, mlp_w2 + (size_t)l * kMLP * kD,
                                               mlp_b2 + (size_t)l * kD, px, px,
                                               kM, kD, kMLP);
    }

    // Final LN on cls rows only (row b lives at x + b*257*768), then head.
    ln_kernel<<<kB, 256>>>(px, pc, norm_g, norm_b, (long)kN * kD, (long)kD);
    head_kernel<<<dim3((kNC + 255) / 256, kB), 256>>>(head_w, head_b, (float*)d_out);
}